// round 2
// baseline (speedup 1.0000x reference)
#include <cuda_runtime.h>
#include <cuda_bf16.h>

#define FULLMASK 0xffffffffu

// XOR swizzle on float4 slot index: makes both transpose access patterns
// bank-conflict-free (verified per 8-lane phase).
__device__ __forceinline__ int swz(int f) { return f ^ ((f >> 3) & 7); }

// In-register butterfly stage over register-index bit MASK.
template <int MASK>
__device__ __forceinline__ void reg_stage(float* v) {
#pragma unroll
    for (int i = 0; i < 32; i++) {
        if (!(i & MASK)) {
            float a = v[i], b = v[i ^ MASK];
            v[i] = a + b;
            v[i ^ MASK] = a - b;
        }
    }
}

// Cross-lane butterfly stage: partner = lane ^ d. One FFMA per element.
__device__ __forceinline__ void shfl_stage(float* v, int d, float sgn) {
#pragma unroll
    for (int i = 0; i < 32; i++) {
        float o = __shfl_xor_sync(FULLMASK, v[i], d);
        v[i] = fmaf(v[i], sgn, o);
    }
}

// One CTA per row. 256 threads (8 warps x 32 lanes), 32 fp32 elements/thread.
// Element-index bit layout per phase:
//   Layout A (load):   i = W*1024 + L*32 + r      (r: bits0-4, L: bits5-9, W: bits10-12)
//   Layout E (mid):    e = rl*1024 + W*128 + L*4 + h   (regs r' = h*8 + rl)
//   Layout S (store):  i = W*1024 + rH*128 + L*4 + rL  (regs r'' = rH*4 + rL)
__global__ __launch_bounds__(256, 4) void fastfood_kernel(
    const float4* __restrict__ x4,   // (rows, 1024) float4
    const float4* __restrict__ B4,   // 2048 float4
    const float4* __restrict__ G4,   // 2048 float4
    const int4*  __restrict__ P4,    // 2048 int4
    float4* __restrict__ out4,       // (rows, 2048) float4
    int rows)
{
    __shared__ float4 sh4[2048];           // 32 KB, holds one full 8192-row
    float* shf = reinterpret_cast<float*>(sh4);

    const int row = blockIdx.x;
    if (row >= rows) return;
    const int W = threadIdx.x >> 5;
    const int L = threadIdx.x & 31;

    float v[32];

    // ---- load x * B (pad 4096 -> 8192 with zeros): layout A ----
    if (W < 4) {
        const float4* xr = x4 + (size_t)row * 1024 + W * 256 + L * 8;
        const float4* br = B4 + W * 256 + L * 8;
#pragma unroll
        for (int q = 0; q < 8; q++) {
            float4 xv = xr[q], bv = br[q];
            v[4 * q + 0] = xv.x * bv.x;
            v[4 * q + 1] = xv.y * bv.y;
            v[4 * q + 2] = xv.z * bv.z;
            v[4 * q + 3] = xv.w * bv.w;
        }
    } else {
#pragma unroll
        for (int i = 0; i < 32; i++) v[i] = 0.0f;
    }

    // ---- FWHT #1 ----
    // element bits 0-4 (register bits)
    reg_stage<1>(v); reg_stage<2>(v); reg_stage<4>(v); reg_stage<8>(v); reg_stage<16>(v);
    // element bits 5-9 (lane bits)
#pragma unroll
    for (int d = 1; d <= 16; d <<= 1) shfl_stage(v, d, (L & d) ? -1.0f : 1.0f);

    // transpose A -> E through shared (swizzled, conflict-free)
#pragma unroll
    for (int q = 0; q < 8; q++)
        sh4[swz(W * 256 + L * 8 + q)] =
            make_float4(v[4 * q + 0], v[4 * q + 1], v[4 * q + 2], v[4 * q + 3]);
    __syncthreads();
#pragma unroll
    for (int rl = 0; rl < 8; rl++) {
        float4 t = sh4[swz(rl * 256 + W * 32 + L)];
        v[rl] = t.x; v[8 + rl] = t.y; v[16 + rl] = t.z; v[24 + rl] = t.w;
    }
    // element bits 10-12 (= rl = reg bits 0-2)
    reg_stage<1>(v); reg_stage<2>(v); reg_stage<4>(v);

    // ---- permutation + G ----
    __syncthreads();
    // scatter F into shared in element order (slot e holds F[e], swizzled)
#pragma unroll
    for (int rl = 0; rl < 8; rl++)
        sh4[swz(rl * 256 + W * 32 + L)] =
            make_float4(v[rl], v[8 + rl], v[16 + rl], v[24 + rl]);
    __syncthreads();
    // gather: out_e = F[perm[e]] * G[e], into layout E for FWHT #2
#pragma unroll
    for (int rl = 0; rl < 8; rl++) {
        int e4 = rl * 256 + W * 32 + L;
        int4 p = P4[e4];
        float4 g = G4[e4];
        v[0  + rl] = shf[(swz(p.x >> 2) << 2) | (p.x & 3)] * g.x;
        v[8  + rl] = shf[(swz(p.y >> 2) << 2) | (p.y & 3)] * g.y;
        v[16 + rl] = shf[(swz(p.z >> 2) << 2) | (p.z & 3)] * g.z;
        v[24 + rl] = shf[(swz(p.w >> 2) << 2) | (p.w & 3)] * g.w;
    }
    __syncthreads();

    // ---- FWHT #2 (layout E) ----
    // element bits 10-12 (rl = reg bits 0-2), bits 0-1 (h = reg bits 3-4)
    reg_stage<1>(v); reg_stage<2>(v); reg_stage<4>(v); reg_stage<8>(v); reg_stage<16>(v);
    // element bits 2-6 (lane bits)
#pragma unroll
    for (int d = 1; d <= 16; d <<= 1) shfl_stage(v, d, (L & d) ? -1.0f : 1.0f);

    // transpose E -> S through shared
#pragma unroll
    for (int rl = 0; rl < 8; rl++)
        sh4[swz(rl * 256 + W * 32 + L)] =
            make_float4(v[rl], v[8 + rl], v[16 + rl], v[24 + rl]);
    __syncthreads();
#pragma unroll
    for (int rH = 0; rH < 8; rH++) {
        float4 t = sh4[swz(W * 256 + rH * 32 + L)];
        v[4 * rH + 0] = t.x; v[4 * rH + 1] = t.y; v[4 * rH + 2] = t.z; v[4 * rH + 3] = t.w;
    }
    // element bits 7-9 (= rH = reg bits 2-4)
    reg_stage<4>(v); reg_stage<8>(v); reg_stage<16>(v);

    // ---- scale (two 1/sqrt(8192) factors folded) + coalesced store ----
    const float S = 1.0f / 8192.0f;
#pragma unroll
    for (int rH = 0; rH < 8; rH++)
        out4[(size_t)row * 2048 + W * 256 + rH * 32 + L] =
            make_float4(v[4 * rH + 0] * S, v[4 * rH + 1] * S,
                        v[4 * rH + 2] * S, v[4 * rH + 3] * S);
}

extern "C" void kernel_launch(void* const* d_in, const int* in_sizes, int n_in,
                              void* d_out, int out_size) {
    const float* x = (const float*)d_in[0];
    const float* B = (const float*)d_in[1];
    const float* G = (const float*)d_in[2];
    const int*   P = (const int*)d_in[3];
    float* out = (float*)d_out;

    int rows = in_sizes[0] / 4096;

    fastfood_kernel<<<rows, 256>>>(
        (const float4*)x, (const float4*)B, (const float4*)G,
        (const int4*)P, (float4*)out, rows);
}

// round 4
// speedup vs baseline: 1.6330x; 1.6330x over previous
#include <cuda_runtime.h>
#include <cuda_bf16.h>

// Bank swizzle: slot(i) = i ^ (bits[9:5] of i) folded into bits[4:0].
// Bijective on [0,8192). Makes every transpose pattern below conflict-free.
__device__ __forceinline__ int sl(int i) { return i ^ ((i >> 5) & 31); }

// In-register butterfly stage over register-index bit MASK, N registers.
template <int N, int MASK>
__device__ __forceinline__ void stage(float* v) {
#pragma unroll
    for (int i = 0; i < N; i++) {
        if (!(i & MASK)) {
            float a = v[i], b = v[i ^ MASK];
            v[i] = a + b;
            v[i ^ MASK] = a - b;
        }
    }
}

// One CTA per row, 256 threads. Phase 1: 4096-pt FWHT (padding identity:
// H_8192 [y;0] = [H_4096 y; H_4096 y]). Phase 2: gather(perm)+G, 8192-pt FWHT.
// All butterflies are register stages; bit groups rotate through registers via
// scalar shared-memory transposes (swizzled, conflict-free). Zero shuffles.
__global__ __launch_bounds__(256, 4) void fastfood_kernel(
    const float4* __restrict__ x4,   // (rows, 1024) float4
    const float4* __restrict__ B4,   // 2048 float4 (only first 1024 used)
    const float4* __restrict__ G4,   // 2048 float4
    const int4*  __restrict__ P4,    // 2048 int4
    float4* __restrict__ out4,       // (rows, 2048) float4
    int rows)
{
    __shared__ float sh[8192];       // 32 KB

    const int row = blockIdx.x;
    if (row >= rows) return;
    const int T = threadIdx.x;
    const int W = T >> 5;            // 3 bits
    const int L = T & 31;            // 5 bits

    float v[32];

    // ================= Phase 1: 4096-point FWHT of y = x*B =================
    // Layout L0: i = (W<<9)|(rq<<7)|(L<<2)|c ; regs r = rq*4+c hold i-bits {0,1,7,8}
    {
        const float4* xr = x4 + (size_t)row * 1024;
#pragma unroll
        for (int rq = 0; rq < 4; rq++) {
            int f4i = (W << 7) | (rq << 5) | L;         // coalesced
            float4 xv = xr[f4i], bv = B4[f4i];
            v[rq * 4 + 0] = xv.x * bv.x;
            v[rq * 4 + 1] = xv.y * bv.y;
            v[rq * 4 + 2] = xv.z * bv.z;
            v[rq * 4 + 3] = xv.w * bv.w;
        }
    }
    stage<16, 1>(v); stage<16, 2>(v); stage<16, 4>(v); stage<16, 8>(v);  // bits 0,1,7,8

    // W1: store in element order (swizzled). Lanes vary i-bits {2..6}: conflict-free.
    {
        int base0 = (W << 9) | (L << 2);
#pragma unroll
        for (int r = 0; r < 16; r++)
            sh[sl(base0 | ((r >> 2) << 7) | (r & 3))] = v[r];
    }
    __syncthreads();

    // R1 -> L1: regs = i-bits {2,3,4,5}; L -> bits {0,1,7,8,9}; W -> bits {6,10,11}
    int base1 = (L & 3) | ((W & 1) << 6) | (((L >> 2) & 7) << 7) | ((W >> 1) << 10);
#pragma unroll
    for (int r = 0; r < 16; r++) v[r] = sh[sl(base1 + (r << 2))];
    stage<16, 1>(v); stage<16, 2>(v); stage<16, 4>(v); stage<16, 8>(v);  // bits 2,3,4,5
    // W2: same slots this thread read — no sync needed before the write.
#pragma unroll
    for (int r = 0; r < 16; r++) sh[sl(base1 + (r << 2))] = v[r];
    __syncthreads();

    // R2 -> L2: regs = i-bits {6,9,10,11}; L -> bits {0..4}; W -> bits {5,7,8}
    int base2 = L | ((W & 1) << 5) | (((W >> 1) & 1) << 7) | ((W >> 2) << 8);
#pragma unroll
    for (int r = 0; r < 16; r++) {
        int off = ((r & 1) << 6) | (((r >> 1) & 1) << 9) |
                  (((r >> 2) & 1) << 10) | ((r >> 3) << 11);
        v[r] = sh[sl(base2 + off)];
    }
    stage<16, 1>(v); stage<16, 2>(v); stage<16, 4>(v); stage<16, 8>(v);  // bits 6,9,10,11
    // W3: write final f back to the same slots (element order, swizzled).
#pragma unroll
    for (int r = 0; r < 16; r++) {
        int off = ((r & 1) << 6) | (((r >> 1) & 1) << 9) |
                  (((r >> 2) & 1) << 10) | ((r >> 3) << 11);
        sh[sl(base2 + off)] = v[r];
    }
    __syncthreads();

    // ================= Permutation + G: F[p] = f[p & 4095] =================
    // Gather into layout L3: e = (W<<10)|(rq<<7)|(L<<2)|c ; regs hold e-bits {0,1,7,8,9}
#pragma unroll
    for (int rq = 0; rq < 8; rq++) {
        int idx4 = (W << 8) | (rq << 5) | L;            // coalesced P/G reads
        int4  p = P4[idx4];
        float4 g = G4[idx4];
        v[(rq << 2) + 0] = sh[sl(p.x & 4095)] * g.x;
        v[(rq << 2) + 1] = sh[sl(p.y & 4095)] * g.y;
        v[(rq << 2) + 2] = sh[sl(p.z & 4095)] * g.z;
        v[(rq << 2) + 3] = sh[sl(p.w & 4095)] * g.w;
    }
    __syncthreads();   // all gathers done before overwriting sh

    // ================= Phase 2: 8192-point FWHT =================
    stage<32, 1>(v); stage<32, 2>(v); stage<32, 4>(v);
    stage<32, 8>(v); stage<32, 16>(v);                   // e-bits 0,1,7,8,9

    // W4: element order. Lanes vary bits {2..6}: conflict-free.
    {
        int base3 = (L << 2) | (W << 10);
#pragma unroll
        for (int r = 0; r < 32; r++)
            sh[sl(base3 | (r & 3) | ((r >> 2) << 7))] = v[r];
    }
    __syncthreads();

    // R4 -> L4: regs = e-bits {2..6}; L -> bits {0,1,7,8,9}; W -> bits {10,11,12}
    int base4 = (L & 3) | (((L >> 2) & 7) << 7) | (W << 10);
#pragma unroll
    for (int r = 0; r < 32; r++) v[r] = sh[sl(base4 + (r << 2))];
    stage<32, 1>(v); stage<32, 2>(v); stage<32, 4>(v);
    stage<32, 8>(v); stage<32, 16>(v);                   // e-bits 2,3,4,5,6
    // W5: same slots, no pre-sync.
#pragma unroll
    for (int r = 0; r < 32; r++) sh[sl(base4 + (r << 2))] = v[r];
    __syncthreads();

    // R5 -> L5: regs = e-bits {0,1,10,11,12}; L -> bits {2..6}; W -> bits {7,8,9}
    int base5 = (L << 2) | (W << 7);
#pragma unroll
    for (int r = 0; r < 32; r++)
        v[r] = sh[sl(base5 | (r & 3) | ((r >> 2) << 10))];
    stage<32, 4>(v); stage<32, 8>(v); stage<32, 16>(v);  // e-bits 10,11,12

    // ================= Scale (1/sqrt(8192) twice) + coalesced store =========
    const float S = 1.0f / 8192.0f;
#pragma unroll
    for (int rh = 0; rh < 8; rh++)
        out4[(size_t)row * 2048 + (rh << 8) + (W << 5) + L] =
            make_float4(v[rh * 4 + 0] * S, v[rh * 4 + 1] * S,
                        v[rh * 4 + 2] * S, v[rh * 4 + 3] * S);
}

extern "C" void kernel_launch(void* const* d_in, const int* in_sizes, int n_in,
                              void* d_out, int out_size) {
    const float* x = (const float*)d_in[0];
    const float* B = (const float*)d_in[1];
    const float* G = (const float*)d_in[2];
    const int*   P = (const int*)d_in[3];
    float* out = (float*)d_out;

    int rows = in_sizes[0] / 4096;

    fastfood_kernel<<<rows, 256>>>(
        (const float4*)x, (const float4*)B, (const float4*)G,
        (const int4*)P, (float4*)out, rows);
}

// round 6
// speedup vs baseline: 1.6337x; 1.0005x over previous
#include <cuda_runtime.h>
#include <cuda_bf16.h>

// Bank swizzle: slot(i) = i ^ (bits[9:5] of i) folded into bits[4:0].
// Bijective on [0,8192). Makes every transpose pattern below conflict-free.
__device__ __forceinline__ int sl(int i) { return i ^ ((i >> 5) & 31); }

// In-register butterfly stage over register-index bit MASK, N registers.
template <int N, int MASK>
__device__ __forceinline__ void stage(float* v) {
#pragma unroll
    for (int i = 0; i < N; i++) {
        if (!(i & MASK)) {
            float a = v[i], b = v[i ^ MASK];
            v[i] = a + b;
            v[i ^ MASK] = a - b;
        }
    }
}

// One CTA per row, 256 threads. Phase 1: 4096-pt FWHT (padding identity:
// H_8192 [y;0] = [H_4096 y; H_4096 y]). Phase 2: gather(perm)+G, 8192-pt FWHT.
// All butterflies are register stages; bit groups rotate through registers via
// scalar shared-memory transposes (swizzled, conflict-free). Zero shuffles.
__global__ __launch_bounds__(256, 4) void fastfood_kernel(
    const float4* __restrict__ x4,   // (rows, 1024) float4
    const float4* __restrict__ B4,   // 2048 float4 (only first 1024 used)
    const float4* __restrict__ G4,   // 2048 float4
    const int4*  __restrict__ P4,    // 2048 int4
    float4* __restrict__ out4,       // (rows, 2048) float4
    int rows)
{
    __shared__ float sh[8192];       // 32 KB

    const int row = blockIdx.x;
    if (row >= rows) return;
    const int T = threadIdx.x;
    const int W = T >> 5;            // 3 bits
    const int L = T & 31;            // 5 bits

    float v[32];

    // ================= Phase 1: 4096-point FWHT of y = x*B =================
    // Layout L0: i = (W<<9)|(rq<<7)|(L<<2)|c ; regs r = rq*4+c hold i-bits {0,1,7,8}
    {
        const float4* xr = x4 + (size_t)row * 1024;
#pragma unroll
        for (int rq = 0; rq < 4; rq++) {
            int f4i = (W << 7) | (rq << 5) | L;         // coalesced
            float4 xv = xr[f4i], bv = B4[f4i];
            v[rq * 4 + 0] = xv.x * bv.x;
            v[rq * 4 + 1] = xv.y * bv.y;
            v[rq * 4 + 2] = xv.z * bv.z;
            v[rq * 4 + 3] = xv.w * bv.w;
        }
    }
    stage<16, 1>(v); stage<16, 2>(v); stage<16, 4>(v); stage<16, 8>(v);  // bits 0,1,7,8

    // W1: store in element order (swizzled). Lanes vary i-bits {2..6}: conflict-free.
    {
        int base0 = (W << 9) | (L << 2);
#pragma unroll
        for (int r = 0; r < 16; r++)
            sh[sl(base0 | ((r >> 2) << 7) | (r & 3))] = v[r];
    }
    __syncthreads();

    // R1 -> L1: regs = i-bits {2,3,4,5}; L -> bits {0,1,7,8,9}; W -> bits {6,10,11}
    int base1 = (L & 3) | ((W & 1) << 6) | (((L >> 2) & 7) << 7) | ((W >> 1) << 10);
#pragma unroll
    for (int r = 0; r < 16; r++) v[r] = sh[sl(base1 + (r << 2))];
    stage<16, 1>(v); stage<16, 2>(v); stage<16, 4>(v); stage<16, 8>(v);  // bits 2,3,4,5
    // W2: same slots this thread read — no sync needed before the write.
#pragma unroll
    for (int r = 0; r < 16; r++) sh[sl(base1 + (r << 2))] = v[r];
    __syncthreads();

    // R2 -> L2: regs = i-bits {6,9,10,11}; L -> bits {0..4}; W -> bits {5,7,8}
    int base2 = L | ((W & 1) << 5) | (((W >> 1) & 1) << 7) | ((W >> 2) << 8);
#pragma unroll
    for (int r = 0; r < 16; r++) {
        int off = ((r & 1) << 6) | (((r >> 1) & 1) << 9) |
                  (((r >> 2) & 1) << 10) | ((r >> 3) << 11);
        v[r] = sh[sl(base2 + off)];
    }
    stage<16, 1>(v); stage<16, 2>(v); stage<16, 4>(v); stage<16, 8>(v);  // bits 6,9,10,11
    // W3: write final f back to the same slots (element order, swizzled).
#pragma unroll
    for (int r = 0; r < 16; r++) {
        int off = ((r & 1) << 6) | (((r >> 1) & 1) << 9) |
                  (((r >> 2) & 1) << 10) | ((r >> 3) << 11);
        sh[sl(base2 + off)] = v[r];
    }
    __syncthreads();

    // ================= Permutation + G: F[p] = f[p & 4095] =================
    // Gather into layout L3: e = (W<<10)|(rq<<7)|(L<<2)|c ; regs hold e-bits {0,1,7,8,9}
#pragma unroll
    for (int rq = 0; rq < 8; rq++) {
        int idx4 = (W << 8) | (rq << 5) | L;            // coalesced P/G reads
        int4  p = P4[idx4];
        float4 g = G4[idx4];
        v[(rq << 2) + 0] = sh[sl(p.x & 4095)] * g.x;
        v[(rq << 2) + 1] = sh[sl(p.y & 4095)] * g.y;
        v[(rq << 2) + 2] = sh[sl(p.z & 4095)] * g.z;
        v[(rq << 2) + 3] = sh[sl(p.w & 4095)] * g.w;
    }
    __syncthreads();   // all gathers done before overwriting sh

    // ================= Phase 2: 8192-point FWHT =================
    stage<32, 1>(v); stage<32, 2>(v); stage<32, 4>(v);
    stage<32, 8>(v); stage<32, 16>(v);                   // e-bits 0,1,7,8,9

    // W4: element order. Lanes vary bits {2..6}: conflict-free.
    {
        int base3 = (L << 2) | (W << 10);
#pragma unroll
        for (int r = 0; r < 32; r++)
            sh[sl(base3 | (r & 3) | ((r >> 2) << 7))] = v[r];
    }
    __syncthreads();

    // R4 -> L4: regs = e-bits {2..6}; L -> bits {0,1,7,8,9}; W -> bits {10,11,12}
    int base4 = (L & 3) | (((L >> 2) & 7) << 7) | (W << 10);
#pragma unroll
    for (int r = 0; r < 32; r++) v[r] = sh[sl(base4 + (r << 2))];
    stage<32, 1>(v); stage<32, 2>(v); stage<32, 4>(v);
    stage<32, 8>(v); stage<32, 16>(v);                   // e-bits 2,3,4,5,6
    // W5: same slots, no pre-sync.
#pragma unroll
    for (int r = 0; r < 32; r++) sh[sl(base4 + (r << 2))] = v[r];
    __syncthreads();

    // R5 -> L5: regs = e-bits {0,1,10,11,12}; L -> bits {2..6}; W -> bits {7,8,9}
    int base5 = (L << 2) | (W << 7);
#pragma unroll
    for (int r = 0; r < 32; r++)
        v[r] = sh[sl(base5 | (r & 3) | ((r >> 2) << 10))];
    stage<32, 4>(v); stage<32, 8>(v); stage<32, 16>(v);  // e-bits 10,11,12

    // ================= Scale (1/sqrt(8192) twice) + coalesced store =========
    const float S = 1.0f / 8192.0f;
#pragma unroll
    for (int rh = 0; rh < 8; rh++)
        out4[(size_t)row * 2048 + (rh << 8) + (W << 5) + L] =
            make_float4(v[rh * 4 + 0] * S, v[rh * 4 + 1] * S,
                        v[rh * 4 + 2] * S, v[rh * 4 + 3] * S);
}

extern "C" void kernel_launch(void* const* d_in, const int* in_sizes, int n_in,
                              void* d_out, int out_size) {
    const float* x = (const float*)d_in[0];
    const float* B = (const float*)d_in[1];
    const float* G = (const float*)d_in[2];
    const int*   P = (const int*)d_in[3];
    float* out = (float*)d_out;

    int rows = in_sizes[0] / 4096;

    fastfood_kernel<<<rows, 256>>>(
        (const float4*)x, (const float4*)B, (const float4*)G,
        (const int4*)P, (float4*)out, rows);
}

// round 7
// speedup vs baseline: 1.7257x; 1.0563x over previous
#include <cuda_runtime.h>
#include <cuda_bf16.h>

// Precomputed gather word-offsets: m2(perm[e] & 4095), m2(i) = i ^ (i[8:6]<<2)
__device__ int g_P2[8192];

__global__ void setup_perm(const int* __restrict__ P) {
    int e = blockIdx.x * 256 + threadIdx.x;
    int q = P[e] & 4095;
    g_P2[e] = q ^ ((q >> 4) & 28);
}

// In-register butterfly stage over register-index bit MASK, N registers.
template <int N, int MASK>
__device__ __forceinline__ void stage(float* v) {
#pragma unroll
    for (int i = 0; i < N; i++) {
        if (!(i & MASK)) {
            float a = v[i], b = v[i ^ MASK];
            v[i] = a + b;
            v[i ^ MASK] = a - b;
        }
    }
}

// One CTA per row, 256 threads (8 warps). Phase 1: 4096-pt FWHT of x*B
// (H_8192[y;0] = [H_4096 y; H_4096 y]). Phase 2: perm-gather * G, 8192-pt FWHT.
// Every shared round-trip uses its own XOR storage map so addresses are
// base ^ compile-time-const (<=1 LOP3/access) and every pattern is
// bank-conflict-free. Gather offsets are precomputed (setup_perm).
__global__ __launch_bounds__(256, 4) void fastfood_kernel(
    const float4* __restrict__ x4,   // (rows, 1024) float4
    const float4* __restrict__ B4,   // 2048 float4 (first 1024 used)
    const float4* __restrict__ G4,   // 2048 float4
    float4* __restrict__ out4,       // (rows, 2048) float4
    int rows)
{
    __shared__ float sh[8192];                       // 32 KB
    float4* sh4 = reinterpret_cast<float4*>(sh);

    const int row = blockIdx.x;
    if (row >= rows) return;
    const int T = threadIdx.x;
    const int W = T >> 5, L = T & 31;
    const int L10 = L & 3, L42 = L >> 2, L210 = L & 7, L43 = L >> 3;

    float v[32];

    // ============ Phase 1: 4096-pt FWHT, i[11:0] ============
    // A1: regs=(rh,c): c=i[1:0], rh=i[11:10]; lanes=i[6:2]; warp=i[9:7]
    {
        const float4* xr = x4 + (size_t)row * 1024;
#pragma unroll
        for (int rh = 0; rh < 4; rh++) {
            int idx = (rh << 8) | (W << 5) | L;      // = i>>2, coalesced
            float4 xv = xr[idx], bv = B4[idx];
            v[rh * 4 + 0] = xv.x * bv.x;
            v[rh * 4 + 1] = xv.y * bv.y;
            v[rh * 4 + 2] = xv.z * bv.z;
            v[rh * 4 + 3] = xv.w * bv.w;
        }
    }
    stage<16, 1>(v); stage<16, 2>(v); stage<16, 4>(v); stage<16, 8>(v); // i 0,1,10,11

    // W1 (vector, identity map): slot = i>>2; phase lanes vary slot&7 = L210.
#pragma unroll
    for (int rh = 0; rh < 4; rh++)
        sh4[(rh << 8) | (W << 5) | L] =
            make_float4(v[rh * 4 + 0], v[rh * 4 + 1], v[rh * 4 + 2], v[rh * 4 + 3]);
    __syncthreads();

    // R1 (scalar): B1: regs=i[8:5], lanes=i[4:0], warp=i[11:9]. word = i.
    {
        int base = (W << 9) | L;
#pragma unroll
        for (int r = 0; r < 16; r++) v[r] = sh[base + (r << 5)];   // imm offsets
    }
    stage<16, 1>(v); stage<16, 2>(v); stage<16, 4>(v); stage<16, 8>(v); // i 5,6,7,8
    __syncthreads();   // W2 writes other threads' R1 words

    // W2 (scalar, map m2(i) = i ^ (i[8:6]<<2); i[8:6]=r[3:1])
    {
        int base = (W << 9) | L;
#pragma unroll
        for (int r = 0; r < 16; r++)
            sh[base ^ ((r << 5) | (((r >> 1) & 7) << 2))] = v[r];
    }
    __syncthreads();

    // R2 (scalar, m2): C1: regs r210=i[4:2], r3=i9; lanes L10=i[1:0], L42=i[8:6];
    //                  warp W0=i5, W21=i[11:10]. word = i ^ (L42<<2).
    int base_r2 = ((W >> 1) << 10) | (L42 << 6) | ((W & 1) << 5) | (L42 << 2) | L10;
#pragma unroll
    for (int r = 0; r < 16; r++)
        v[r] = sh[base_r2 ^ ((((r >> 3) & 1) << 9) | ((r & 7) << 2))];
    stage<16, 1>(v); stage<16, 2>(v); stage<16, 4>(v); stage<16, 8>(v); // i 2,3,4,9
    // W3: final f at m2(i) — same addresses this thread just read (no pre-sync).
#pragma unroll
    for (int r = 0; r < 16; r++)
        sh[base_r2 ^ ((((r >> 3) & 1) << 9) | ((r & 7) << 2))] = v[r];
    __syncthreads();

    // ============ Permutation + G (precomputed offsets) ============
    // A2: e = (W<<10)|(rh<<7)|(L<<2)|c ; regs=(rh,c): c=e[1:0], rh=e[9:7]
    {
        const int4* P2_4 = reinterpret_cast<const int4*>(g_P2);
#pragma unroll
        for (int rh = 0; rh < 8; rh++) {
            int meta = (W << 8) | (rh << 5) | L;     // = e>>2, coalesced
            int4  p = P2_4[meta];
            float4 g = G4[meta];
            v[rh * 4 + 0] = sh[p.x] * g.x;
            v[rh * 4 + 1] = sh[p.y] * g.y;
            v[rh * 4 + 2] = sh[p.z] * g.z;
            v[rh * 4 + 3] = sh[p.w] * g.w;
        }
    }
    __syncthreads();   // all gathers done before W4 overwrites

    // ============ Phase 2: 8192-pt FWHT, e[12:0] ============
    stage<32, 1>(v); stage<32, 2>(v); stage<32, 4>(v);
    stage<32, 8>(v); stage<32, 16>(v);               // e 0,1,7,8,9

    // Storage map for trips 4/5:
    // w(e) = (e[12:10]<<10)|(e[6:5]<<8)|(e[9:7]<<5)|((e[4:2]^e[9:7])<<2)|e[1:0]
    // W4 (vector): slot = (W<<8)|(L43<<6)|(rh<<3)|(L210^rh); slot&7 varies in phase.
    {
        int baseW4 = (W << 8) | (L43 << 6) | L210;
#pragma unroll
        for (int rh = 0; rh < 8; rh++)
            sh4[baseW4 ^ (rh * 9)] =
                make_float4(v[rh * 4 + 0], v[rh * 4 + 1], v[rh * 4 + 2], v[rh * 4 + 3]);
    }
    __syncthreads();

    // R4 (scalar): B2: regs r=e[6:2]; lanes L10=e[1:0], L42=e[9:7]; warp=e[12:10].
    int baseR4 = (W << 10) | (L42 << 5) | (L42 << 2) | L10;
#pragma unroll
    for (int r = 0; r < 32; r++)
        v[r] = sh[baseR4 ^ (((r >> 3) << 8) | ((r & 7) << 2))];
    stage<32, 1>(v); stage<32, 2>(v); stage<32, 4>(v);
    stage<32, 8>(v); stage<32, 16>(v);               // e 2,3,4,5,6
    // W5: same addresses (no pre-sync).
#pragma unroll
    for (int r = 0; r < 32; r++)
        sh[baseR4 ^ (((r >> 3) << 8) | ((r & 7) << 2))] = v[r];
    __syncthreads();

    // R5 (vector): C2: regs=(rp,c): c=e[1:0], rp=e[12:10]; lanes=e[6:2]; warp=e[9:7].
    // slot = (rp<<8)|(L43<<6)|(W<<3)|(L210^W): immediate offsets per rp.
    {
        int baseR5 = (L43 << 6) | (W << 3) | (L210 ^ W);
#pragma unroll
        for (int rp = 0; rp < 8; rp++) {
            float4 t = sh4[baseR5 + (rp << 8)];
            v[rp * 4 + 0] = t.x; v[rp * 4 + 1] = t.y;
            v[rp * 4 + 2] = t.z; v[rp * 4 + 3] = t.w;
        }
    }
    stage<32, 4>(v); stage<32, 8>(v); stage<32, 16>(v); // e 10,11,12

    // ============ Scale + coalesced store ============
    const float S = 1.0f / 8192.0f;
#pragma unroll
    for (int rp = 0; rp < 8; rp++)
        out4[(size_t)row * 2048 + (rp << 8) + (W << 5) + L] =
            make_float4(v[rp * 4 + 0] * S, v[rp * 4 + 1] * S,
                        v[rp * 4 + 2] * S, v[rp * 4 + 3] * S);
}

extern "C" void kernel_launch(void* const* d_in, const int* in_sizes, int n_in,
                              void* d_out, int out_size) {
    const float* x = (const float*)d_in[0];
    const float* B = (const float*)d_in[1];
    const float* G = (const float*)d_in[2];
    const int*   P = (const int*)d_in[3];
    float* out = (float*)d_out;

    int rows = in_sizes[0] / 4096;

    setup_perm<<<32, 256>>>(P);
    fastfood_kernel<<<rows, 256>>>(
        (const float4*)x, (const float4*)B, (const float4*)G,
        (float4*)out, rows);
}